// round 2
// baseline (speedup 1.0000x reference)
#include <cuda_runtime.h>
#include <cuda_bf16.h>

#define NEG_INF (-1e10f)

// Problem constants
#define BB 32
#define TT 1000
#define HH 512
#define VV 2048
#define LL 100
#define SS 201
#define MROWS (BB*TT)          // 32000
#define MPAD  (MROWS + 64)     // padding for DP prefetch overrun

// ---------------- static device scratch (no allocation allowed) ----------------
__device__ __align__(16) static __nv_bfloat16 g_X[MROWS * HH];        // eouts bf16
__device__ __align__(16) static __nv_bfloat16 g_W[VV * HH];           // W bf16
__device__ __align__(16) static __nv_bfloat16 g_Wlab[BB * 128 * HH];  // gathered label weights
__device__ __align__(16) static float         g_blab[BB * 128];       // gathered label bias
__device__ __align__(16) static float         g_sumexp[MPAD];         // per-row sum(exp(logit))
__device__ __align__(16) static float         g_lab[(size_t)MPAD * 128]; // label logits [b*T+t][128]

// ---------------- helpers ----------------
__device__ __forceinline__ unsigned smem_u32(const void* p) {
    return (unsigned)__cvta_generic_to_shared(p);
}

#define CP_ASYNC16(dst, src) \
    asm volatile("cp.async.ca.shared.global [%0], [%1], 16;\n" :: "r"(dst), "l"(src) : "memory")
#define CP_ASYNC4(dst, src) \
    asm volatile("cp.async.ca.shared.global [%0], [%1], 4;\n" :: "r"(dst), "l"(src) : "memory")
#define CP_COMMIT() asm volatile("cp.async.commit_group;\n" ::: "memory")
#define CP_WAIT1()  asm volatile("cp.async.wait_group 1;\n" ::: "memory")

__device__ __forceinline__ void ldmatrix_x4(unsigned* r, unsigned addr) {
    asm volatile("ldmatrix.sync.aligned.m8n8.x4.shared.b16 {%0,%1,%2,%3}, [%4];\n"
                 : "=r"(r[0]), "=r"(r[1]), "=r"(r[2]), "=r"(r[3]) : "r"(addr));
}

__device__ __forceinline__ void mma_bf16(float* d, const unsigned* a, unsigned b0, unsigned b1) {
    asm volatile("mma.sync.aligned.m16n8k16.row.col.f32.bf16.bf16.f32 "
                 "{%0,%1,%2,%3}, {%4,%5,%6,%7}, {%8,%9}, {%0,%1,%2,%3};\n"
                 : "+f"(d[0]), "+f"(d[1]), "+f"(d[2]), "+f"(d[3])
                 : "r"(a[0]), "r"(a[1]), "r"(a[2]), "r"(a[3]), "r"(b0), "r"(b1));
}

// ---------------- kernel 1: convert + gather + zero scratch/out ----------------
__global__ void prep_kernel(const float* __restrict__ eouts, const float* __restrict__ W,
                            const float* __restrict__ bias, const int* __restrict__ ys,
                            float* __restrict__ out, int out_size) {
    int i = blockIdx.x * blockDim.x + threadIdx.x;
    int stride = gridDim.x * blockDim.x;
    for (int k = i; k < MROWS * HH; k += stride) g_X[k] = __float2bfloat16(eouts[k]);
    for (int k = i; k < VV * HH; k += stride)    g_W[k] = __float2bfloat16(W[k]);
    // gathered label weights: j=0 -> blank(0), j=1..100 -> ys[b][j-1], j>=101 -> 0
    for (int k = i; k < BB * 128 * HH; k += stride) {
        int kk = k & (HH - 1);
        int j  = (k >> 9) & 127;
        int b  = k >> 16;
        int v  = (j == 0) ? 0 : ((j <= LL) ? ys[b * LL + (j - 1)] : -1);
        g_Wlab[k] = (v >= 0) ? __float2bfloat16(W[(size_t)v * HH + kk]) : __float2bfloat16(0.0f);
    }
    for (int k = i; k < BB * 128; k += stride) {
        int j = k & 127;
        int b = k >> 7;
        int v = (j == 0) ? 0 : ((j <= LL) ? ys[b * LL + (j - 1)] : -1);
        g_blab[k] = (v >= 0) ? bias[v] : 0.0f;
    }
    for (int k = i; k < MPAD; k += stride) g_sumexp[k] = 0.0f;
    for (int k = i; k < out_size; k += stride) out[k] = 0.0f;
}

// ---------------- kernel 2/3: bf16 tensor-core GEMM (templated epilogue) ----------------
// MODE 0: full-V GEMM, epilogue reduces sum(exp(logit+bias)) per row -> atomicAdd g_sumexp
// MODE 1: label GEMM per batch, epilogue stores logit+bias to g_lab
template <int MODE>
__global__ __launch_bounds__(256)
void gemm_kernel(const float* __restrict__ bias) {
    __shared__ __nv_bfloat16 As[2][128 * 24];
    __shared__ __nv_bfloat16 Bs[2][128 * 24];

    const int tid = threadIdx.x, lane = tid & 31, wid = tid >> 5;
    const int wm = (wid & 3) * 32;   // warp m offset within 128
    const int wn = (wid >> 2) * 64;  // warp n offset within 128

    const int ldrow = tid >> 1;         // 0..127
    const int ldcol = (tid & 1) * 8;    // 0 or 8 (bf16 elems)

    const __nv_bfloat16* Ag;
    const __nv_bfloat16* Bg;
    int bb = 0;
    if (MODE == 0) {
        Ag = g_X + (size_t)(blockIdx.x * 128 + ldrow) * HH + ldcol;
        Bg = g_W + (size_t)(blockIdx.y * 128 + ldrow) * HH + ldcol;
    } else {
        bb = blockIdx.y;
        int t = blockIdx.x * 128 + ldrow;
        if (t > TT - 1) t = TT - 1;  // clamp (values unused)
        Ag = g_X    + (size_t)(bb * TT + t) * HH + ldcol;
        Bg = g_Wlab + (size_t)(bb * 128 + ldrow) * HH + ldcol;
    }
    const int soff = ldrow * 24 + ldcol;

    float d[2][8][4];
#pragma unroll
    for (int mi = 0; mi < 2; mi++)
#pragma unroll
        for (int nj = 0; nj < 8; nj++)
#pragma unroll
            for (int q = 0; q < 4; q++) d[mi][nj][q] = 0.0f;

    // ldmatrix source addresses (buffer 0); buffer stride = 128*24*2 = 6144 bytes
    unsigned aAddr[2], bAddr[4];
#pragma unroll
    for (int mi = 0; mi < 2; mi++)
        aAddr[mi] = smem_u32(&As[0][(wm + mi * 16 + (lane & 15)) * 24 + (lane >> 4) * 8]);
#pragma unroll
    for (int np = 0; np < 4; np++) {
        int r = wn + np * 16 + (lane & 7) + ((lane >> 4) & 1) * 8;
        int c = ((lane >> 3) & 1) * 8;
        bAddr[np] = smem_u32(&Bs[0][r * 24 + c]);
    }

    // prologue: stage k-tiles 0 and 1
    {
        CP_ASYNC16(smem_u32(&As[0][soff]), Ag + 0);
        CP_ASYNC16(smem_u32(&Bs[0][soff]), Bg + 0);
        CP_COMMIT();
        CP_ASYNC16(smem_u32(&As[1][soff]), Ag + 16);
        CP_ASYNC16(smem_u32(&Bs[1][soff]), Bg + 16);
        CP_COMMIT();
    }

    for (int kt = 0; kt < HH / 16; kt++) {
        CP_WAIT1();
        __syncthreads();
        const int buf = kt & 1;
        const unsigned off = buf * 6144u;

        unsigned ra[2][4], rb[4][4];
#pragma unroll
        for (int mi = 0; mi < 2; mi++) ldmatrix_x4(ra[mi], aAddr[mi] + off);
#pragma unroll
        for (int np = 0; np < 4; np++) ldmatrix_x4(rb[np], bAddr[np] + off);
        __syncthreads();

        if (kt + 2 < HH / 16) {
            int k0 = (kt + 2) * 16;
            CP_ASYNC16(smem_u32(&As[buf][soff]), Ag + k0);
            CP_ASYNC16(smem_u32(&Bs[buf][soff]), Bg + k0);
            CP_COMMIT();
        } else {
            CP_COMMIT();
        }

#pragma unroll
        for (int mi = 0; mi < 2; mi++)
#pragma unroll
            for (int nj = 0; nj < 8; nj++) {
                int np = nj >> 1;
                unsigned b0 = (nj & 1) ? rb[np][2] : rb[np][0];
                unsigned b1 = (nj & 1) ? rb[np][3] : rb[np][1];
                mma_bf16(d[mi][nj], ra[mi], b0, b1);
            }
    }

    // ---------------- epilogue ----------------
    if (MODE == 0) {
#pragma unroll
        for (int mi = 0; mi < 2; mi++) {
            float se0 = 0.0f, se1 = 0.0f;
            int r = blockIdx.x * 128 + wm + mi * 16 + (lane >> 2);
#pragma unroll
            for (int nj = 0; nj < 8; nj++) {
                int c = blockIdx.y * 128 + wn + nj * 8 + (lane & 3) * 2;
                float b0 = __ldg(&bias[c]);
                float b1 = __ldg(&bias[c + 1]);
                se0 += __expf(d[mi][nj][0] + b0) + __expf(d[mi][nj][1] + b1);
                se1 += __expf(d[mi][nj][2] + b0) + __expf(d[mi][nj][3] + b1);
            }
            se0 += __shfl_xor_sync(0xffffffffu, se0, 1);
            se0 += __shfl_xor_sync(0xffffffffu, se0, 2);
            se1 += __shfl_xor_sync(0xffffffffu, se1, 1);
            se1 += __shfl_xor_sync(0xffffffffu, se1, 2);
            if ((lane & 3) == 0) {
                atomicAdd(&g_sumexp[r], se0);
                atomicAdd(&g_sumexp[r + 8], se1);
            }
        }
    } else {
#pragma unroll
        for (int mi = 0; mi < 2; mi++) {
            int trow = blockIdx.x * 128 + wm + mi * 16 + (lane >> 2);
#pragma unroll
            for (int nj = 0; nj < 8; nj++) {
                int c = wn + nj * 8 + (lane & 3) * 2;
                float bl0 = g_blab[bb * 128 + c];
                float bl1 = g_blab[bb * 128 + c + 1];
                if (trow < TT) {
                    float2 v = make_float2(d[mi][nj][0] + bl0, d[mi][nj][1] + bl1);
                    *(float2*)&g_lab[(size_t)(bb * TT + trow) * 128 + c] = v;
                }
                if (trow + 8 < TT) {
                    float2 v = make_float2(d[mi][nj][2] + bl0, d[mi][nj][3] + bl1);
                    *(float2*)&g_lab[(size_t)(bb * TT + trow + 8) * 128 + c] = v;
                }
            }
        }
    }
}

// ---------------- kernel 4: CTC forward DP (one block per batch item) ----------------
__global__ __launch_bounds__(256)
void ctc_dp_kernel(const int* __restrict__ ys, const int* __restrict__ elens,
                   const int* __restrict__ ylens, float* __restrict__ out) {
    const int b = blockIdx.x;
    const int tid = threadIdx.x;
    const int s = tid;

    __shared__ float abuf[2][224];
    __shared__ float4 lab_s[2][16][26];   // staged label logits, 104 floats/frame
    __shared__ float  se_s[2][16];
    __shared__ float  lse_s[2][16];

    const int ylen = ylens[b];
    const int tend = elens[b] - 1;        // alphas index of final frame

    const bool in_s  = (s < SS);
    const bool valid = in_s && (s <= 2 * ylen);
    const int  li    = (s & 1) ? (s >> 1) + 1 : 0;
    bool skip = false;
    if (in_s && (s & 1) && s >= 3)
        skip = (ys[b * LL + (s >> 1)] != ys[b * LL + (s >> 1) - 1]);

    // t = 0 init
    float aself = NEG_INF;
    if (s < 2) {
        float lse0 = __logf(g_sumexp[b * TT]);
        aself = g_lab[(size_t)(b * TT) * 128 + li] - lse0;
        if (!valid) aself = NEG_INF;
    }
    if (in_s) abuf[0][s] = aself;
    if (!in_s) aself = NEG_INF;

    // stage helper (chunk c = frames [1+16c, 1+16c+16) )
    auto stage = [&](int c, int bf) {
        int t0 = 1 + c * 16;
        for (int idx = tid; idx < 16 * 26; idx += 256) {
            int j = idx / 26;
            int q = idx - j * 26;
            size_t row = (size_t)b * TT + t0 + j;   // padded buffers make this safe
            CP_ASYNC16(smem_u32(&lab_s[bf][j][q]), &g_lab[row * 128 + q * 4]);
        }
        if (tid < 16) CP_ASYNC4(smem_u32(&se_s[bf][tid]), &g_sumexp[b * TT + t0 + tid]);
        CP_COMMIT();
    };

    stage(0, 0);
    stage(1, 1);

    int p = 0;
    int t = 1, c = 0;
    while (t <= tend) {
        CP_WAIT1();
        __syncthreads();           // chunk c staged + abuf[p] visible
        const int bf = c & 1;
        if (tid < 16) lse_s[bf][tid] = __logf(se_s[bf][tid]);
        __syncthreads();

        const int jmax = min(16, tend - t + 1);
        for (int j = 0; j < jmax; j++) {
            float lp = 0.0f, a2 = NEG_INF, a3 = NEG_INF;
            if (in_s) {
                lp = ((const float*)&lab_s[bf][j][0])[li] - lse_s[bf][j];
                if (s >= 1) a2 = abuf[p][s - 1];
                if (skip)   a3 = abuf[p][s - 2];
            }
            float a1 = aself;
            float m = fmaxf(a1, fmaxf(a2, a3));
            float sum = __expf(a1 - m) + __expf(a2 - m) + __expf(a3 - m);
            float nv = m + __logf(sum) + lp;
            nv = valid ? nv : NEG_INF;
            if (in_s) abuf[p ^ 1][s] = nv;
            aself = in_s ? nv : NEG_INF;
            p ^= 1;
            __syncthreads();
        }
        stage(c + 2, bf);          // refill the buffer we just consumed
        t += 16;
        c += 1;
    }

    if (tid == 0) {
        float last = abuf[p][2 * ylen];
        float prev = abuf[p][2 * ylen - 1];
        float m = fmaxf(last, prev);
        float l = -(m + __logf(__expf(last - m) + __expf(prev - m)));
        if (!(l < -0.5f * NEG_INF)) l = 0.0f;   // zero_infinity
        atomicAdd(out, l * (1.0f / (float)BB));
    }
}

// ---------------- launch ----------------
extern "C" void kernel_launch(void* const* d_in, const int* in_sizes, int n_in,
                              void* d_out, int out_size) {
    const float* eouts = (const float*)d_in[0];
    const float* W     = (const float*)d_in[1];
    const float* bias  = (const float*)d_in[2];
    const int*   ys    = (const int*)d_in[3];
    const int*   elens = (const int*)d_in[4];
    const int*   ylens = (const int*)d_in[5];
    float* out = (float*)d_out;

    prep_kernel<<<2048, 256>>>(eouts, W, bias, ys, out, out_size);
    gemm_kernel<0><<<dim3(MROWS / 128, VV / 128), 256>>>(bias);
    gemm_kernel<1><<<dim3(8, BB), 256>>>(bias);
    ctc_dp_kernel<<<BB, 256>>>(ys, elens, ylens, out);
}